// round 10
// baseline (speedup 1.0000x reference)
#include <cuda_runtime.h>

// Problem constants
#define NMAX 50000
#define EMAX 1000000
#define RNUM 8
#define BNUM 30
#define JTOT 576            // 8*64 relation cols + 64 self-loop cols
#define NSEG (NMAX * RNUM)  // 400000 (dst,relation) segments
#define SCHUNK 512
#define NBLK2 782           // ceil(400000/512)
#define NPAD2 (NBLK2 * SCHUNK)   // 400384

// ---------------- static device scratch ----------------
__device__ float g_Wcat[JTOT * 64];              // [kk][o]
__device__ float g_z[(size_t)NMAX * JTOT];       // per-dst relation sums | self x
__device__ float g_g[(size_t)NMAX * 64];         // ((z@Wcat+b1)*s) @ W2
__device__ int   g_deg_out[NMAX];
__device__ int   g_deg[NPAD2];                   // per-(dst,rel) counts, zero-padded
__device__ int   g_cursor[NSEG];
__device__ int   g_rowoff[NSEG + 1];
__device__ int   g_bsum[NBLK2];
__device__ int   g_boff[NBLK2];
__device__ int   g_csr[EMAX];                    // bare src index

// ---------------- f32x2 packed-FMA helpers ----------------
typedef unsigned long long ull;
__device__ __forceinline__ ull pack2(float lo, float hi) {
    ull r; asm("mov.b64 %0,{%1,%2};" : "=l"(r) : "f"(lo), "f"(hi)); return r;
}
__device__ __forceinline__ void unpack2(ull v, float& lo, float& hi) {
    asm("mov.b64 {%0,%1},%2;" : "=f"(lo), "=f"(hi) : "l"(v));
}
__device__ __forceinline__ void ffma2(ull& d, ull a, ull b) {
    asm("fma.rn.f32x2 %0,%1,%2,%0;" : "+l"(d) : "l"(a), "l"(b));
}

// ---------------- K0: zero counters ----------------
__global__ void zero_kernel(int n) {
    int i = blockIdx.x * blockDim.x + threadIdx.x;
    if (i < NPAD2) g_deg[i] = 0;
    if (i < NSEG) g_cursor[i] = 0;
    if (i < n) g_deg_out[i] = 0;
    if (i == 0) g_rowoff[0] = 0;
}

// ---------------- K1: Wcat ----------------
__global__ void wcat_kernel(const float* __restrict__ basis,
                            const float* __restrict__ comp,
                            const float* __restrict__ loopw) {
    int idx = blockIdx.x * blockDim.x + threadIdx.x;
    if (idx >= JTOT * 64) return;
    int o = idx & 63;
    int kk = idx >> 6;
    if (kk < RNUM * 64) {
        int r = kk >> 6, i = kk & 63;
        float s = 0.f;
#pragma unroll
        for (int b = 0; b < BNUM; b++)
            s += comp[r * BNUM + b] * basis[(b * 64 + i) * 64 + o];
        g_Wcat[kk * 64 + o] = s;
    } else {
        int i = kk - RNUM * 64;
        g_Wcat[kk * 64 + o] = loopw[i * 64 + o];
    }
}

// ---------------- K2: counts per (dst,rel) + out-degree, 2 edges/thread ----------------
__global__ void deg_kernel(const int* __restrict__ ei,
                           const int* __restrict__ et, int e) {
    int i2 = (blockIdx.x * blockDim.x + threadIdx.x) * 2;
    if (i2 + 1 < e) {
        int2 s = *(const int2*)&ei[i2];
        int2 d = *(const int2*)&ei[e + i2];
        int2 r = *(const int2*)&et[i2];
        atomicAdd(&g_deg_out[s.x], 1);
        atomicAdd(&g_deg_out[s.y], 1);
        atomicAdd(&g_deg[d.x * RNUM + r.x], 1);
        atomicAdd(&g_deg[d.y * RNUM + r.y], 1);
    } else if (i2 < e) {
        atomicAdd(&g_deg_out[ei[i2]], 1);
        atomicAdd(&g_deg[ei[e + i2] * RNUM + et[i2]], 1);
    }
}

// ---------------- K3a: per-block sums ----------------
__global__ void scan1_kernel() {
    __shared__ int ws[8];
    int b = blockIdx.x, tid = threadIdx.x, lane = tid & 31, wid = tid >> 5;
    int2 v = *(const int2*)&g_deg[b * SCHUNK + tid * 2];
    int s = v.x + v.y;
#pragma unroll
    for (int off = 16; off >= 1; off >>= 1)
        s += __shfl_down_sync(0xFFFFFFFFu, s, off);
    if (lane == 0) ws[wid] = s;
    __syncthreads();
    if (tid == 0) {
        int t = 0;
#pragma unroll
        for (int j = 0; j < 8; j++) t += ws[j];
        g_bsum[b] = t;
    }
}

// ---------------- K3b: exclusive scan of block sums ----------------
__global__ void scan2_kernel() {
    __shared__ int wsum[32];
    int tid = threadIdx.x, lane = tid & 31, wid = tid >> 5;
    int v = (tid < NBLK2) ? g_bsum[tid] : 0;
    int sc = v;
#pragma unroll
    for (int off = 1; off < 32; off <<= 1) {
        int t = __shfl_up_sync(0xFFFFFFFFu, sc, off);
        if (lane >= off) sc += t;
    }
    if (lane == 31) wsum[wid] = sc;
    __syncthreads();
    if (wid == 0) {
        int w = wsum[lane];
        int s2 = w;
#pragma unroll
        for (int off = 1; off < 32; off <<= 1) {
            int t = __shfl_up_sync(0xFFFFFFFFu, s2, off);
            if (lane >= off) s2 += t;
        }
        wsum[lane] = s2 - w;
    }
    __syncthreads();
    if (tid < NBLK2) g_boff[tid] = sc - v + wsum[wid];
}

// ---------------- K3c: per-block scan + offset -> rowoff ----------------
__global__ void scan3_kernel() {
    __shared__ int ws[8];
    __shared__ int wx[8];
    int b = blockIdx.x, tid = threadIdx.x, lane = tid & 31, wid = tid >> 5;
    int i0 = b * SCHUNK + tid * 2;
    int2 v = *(const int2*)&g_deg[i0];
    int ps = v.x + v.y;
    int sc = ps;
#pragma unroll
    for (int off = 1; off < 32; off <<= 1) {
        int t = __shfl_up_sync(0xFFFFFFFFu, sc, off);
        if (lane >= off) sc += t;
    }
    if (lane == 31) ws[wid] = sc;
    __syncthreads();
    if (tid == 0) {
        int run = 0;
#pragma unroll
        for (int j = 0; j < 8; j++) { wx[j] = run; run += ws[j]; }
    }
    __syncthreads();
    int excl = (sc - ps) + wx[wid] + g_boff[b];
    int r1 = excl + v.x;
    int r2 = r1 + v.y;
    if (i0 < NSEG)     g_rowoff[i0 + 1] = r1;
    if (i0 + 1 < NSEG) g_rowoff[i0 + 2] = r2;
}

// ---------------- K4: fill CSR, 2 edges/thread ----------------
__global__ void fill_kernel(const int* __restrict__ ei,
                            const int* __restrict__ et, int e) {
    int i2 = (blockIdx.x * blockDim.x + threadIdx.x) * 2;
    if (i2 + 1 < e) {
        int2 s = *(const int2*)&ei[i2];
        int2 d = *(const int2*)&ei[e + i2];
        int2 r = *(const int2*)&et[i2];
        int seg0 = d.x * RNUM + r.x;
        int seg1 = d.y * RNUM + r.y;
        int pos0 = g_rowoff[seg0] + atomicAdd(&g_cursor[seg0], 1);
        int pos1 = g_rowoff[seg1] + atomicAdd(&g_cursor[seg1], 1);
        g_csr[pos0] = s.x;
        g_csr[pos1] = s.y;
    } else if (i2 < e) {
        int seg = ei[e + i2] * RNUM + et[i2];
        int pos = g_rowoff[seg] + atomicAdd(&g_cursor[seg], 1);
        g_csr[pos] = ei[i2];
    }
}

// ---------------- K5: aggregate x[src] per (dst,rel) segment -> z ----------------
__global__ void aggz_kernel(const float* __restrict__ x, int n) {
    int gw   = (blockIdx.x * blockDim.x + threadIdx.x) >> 5;
    int lane = threadIdx.x & 31;
    if (gw >= n) return;
    float* zr = &g_z[(size_t)gw * JTOT];
    int base = gw * RNUM;
    int beg = g_rowoff[base];
#pragma unroll 1
    for (int r = 0; r < RNUM; r++) {
        int end = g_rowoff[base + r + 1];
        float a0 = 0.f, a1 = 0.f;
        int e = beg;
        for (; e + 1 < end; e += 2) {
            int p0 = g_csr[e], p1 = g_csr[e + 1];
            const float* s0 = &x[(size_t)p0 * 64];
            const float* s1 = &x[(size_t)p1 * 64];
            float v00 = s0[lane],      v10 = s1[lane];
            float v01 = s0[lane + 32], v11 = s1[lane + 32];
            a0 += v00 + v10;
            a1 += v01 + v11;
        }
        if (e < end) {
            const float* s0 = &x[(size_t)g_csr[e] * 64];
            a0 += s0[lane];
            a1 += s0[lane + 32];
        }
        zr[r * 64 + lane]      = a0;
        zr[r * 64 + lane + 32] = a1;
        beg = end;
    }
    zr[512 + lane]      = x[(size_t)gw * 64 + lane];
    zr[512 + lane + 32] = x[(size_t)gw * 64 + lane + 32];
}

// ---------------- K6: FUSED GEMM: g = ((z@Wcat + b1)*rsqrt(deg_out)) @ W2 ----------------
__global__ __launch_bounds__(256) void gemmf_kernel(const float* __restrict__ bias1,
                                                    const float* __restrict__ w2,
                                                    int n) {
    __shared__ float shA[32][132];   // [k][m], padded; reused as hs chunk in phase B
    __shared__ float shB[32][64];    // B chunk; reused for W2 chunks in phase B

    int tid = threadIdx.x;
    int tx = tid & 15, ty = tid >> 4;
    int mBase = blockIdx.x * 128;
    int rowL = tid >> 1, half = tid & 1;
    int gr = mBase + rowL;

    // ---- phase 1: acc = z[128 x 576] @ Wcat[576 x 64] ----
    ull acc[4][4] = {};
    for (int k0 = 0; k0 < JTOT; k0 += 32) {
        __syncthreads();
#pragma unroll
        for (int q = 0; q < 4; q++) {
            int kk = half * 16 + q * 4;
            float4 v = make_float4(0.f, 0.f, 0.f, 0.f);
            if (gr < n) v = *(const float4*)&g_z[(size_t)gr * JTOT + k0 + kk];
            shA[kk][rowL] = v.x; shA[kk + 1][rowL] = v.y;
            shA[kk + 2][rowL] = v.z; shA[kk + 3][rowL] = v.w;
        }
        {
            int f = tid * 8, kr = f >> 6, c = f & 63;
            *(float4*)&shB[kr][c]     = *(const float4*)&g_Wcat[(size_t)(k0 + kr) * 64 + c];
            *(float4*)&shB[kr][c + 4] = *(const float4*)&g_Wcat[(size_t)(k0 + kr) * 64 + c + 4];
        }
        __syncthreads();
#pragma unroll
        for (int k = 0; k < 32; k++) {
            float4 b = *(const float4*)&shB[k][tx * 4];
            ull bd0 = pack2(b.x, b.x), bd1 = pack2(b.y, b.y);
            ull bd2 = pack2(b.z, b.z), bd3 = pack2(b.w, b.w);
#pragma unroll
            for (int i = 0; i < 4; i++) {
                ull a = *(const ull*)&shA[k][ty * 8 + 2 * i];
                ffma2(acc[i][0], a, bd0);
                ffma2(acc[i][1], a, bd1);
                ffma2(acc[i][2], a, bd2);
                ffma2(acc[i][3], a, bd3);
            }
        }
    }

    // ---- epilogue 1 in registers: hs = (acc + bias1) * rsqrt(deg_out) ----
    float4 b1v = *(const float4*)&bias1[tx * 4];
    float bj[4] = { b1v.x, b1v.y, b1v.z, b1v.w };
#pragma unroll
    for (int i = 0; i < 4; i++) {
        int g0 = mBase + ty * 8 + 2 * i, g1 = g0 + 1;
        float s0 = (g0 < n) ? rsqrtf((float)max(g_deg_out[g0], 1)) : 0.f;
        float s1 = (g1 < n) ? rsqrtf((float)max(g_deg_out[g1], 1)) : 0.f;
#pragma unroll
        for (int j = 0; j < 4; j++) {
            float lo, hi;
            unpack2(acc[i][j], lo, hi);
            acc[i][j] = pack2((lo + bj[j]) * s0, (hi + bj[j]) * s1);
        }
    }

    // ---- phase B: g = hs[128 x 64] @ W2[64 x 64], hs staged 32-k at a time ----
    ull acc2[4][4] = {};
#pragma unroll 1
    for (int c2 = 0; c2 < 2; c2++) {
        __syncthreads();
        // stash this chunk's hs columns: threads whose tx-cols fall in [c2*32, c2*32+32)
        if ((tx >> 3) == c2) {
            int kb = tx * 4 - c2 * 32;   // 0,4,...,28
#pragma unroll
            for (int j = 0; j < 4; j++) {
#pragma unroll
                for (int i = 0; i < 4; i++) {
                    float lo, hi;
                    unpack2(acc[i][j], lo, hi);
                    shA[kb + j][ty * 8 + 2 * i]     = lo;
                    shA[kb + j][ty * 8 + 2 * i + 1] = hi;
                }
            }
        }
        // stage W2 chunk [32][64]
        {
            int f = tid * 8, kr = f >> 6, c = f & 63;
            *(float4*)&shB[kr][c]     = *(const float4*)&w2[(size_t)(c2 * 32 + kr) * 64 + c];
            *(float4*)&shB[kr][c + 4] = *(const float4*)&w2[(size_t)(c2 * 32 + kr) * 64 + c + 4];
        }
        __syncthreads();
#pragma unroll
        for (int k = 0; k < 32; k++) {
            float4 b = *(const float4*)&shB[k][tx * 4];
            ull bd0 = pack2(b.x, b.x), bd1 = pack2(b.y, b.y);
            ull bd2 = pack2(b.z, b.z), bd3 = pack2(b.w, b.w);
#pragma unroll
            for (int i = 0; i < 4; i++) {
                ull a = *(const ull*)&shA[k][ty * 8 + 2 * i];
                ffma2(acc2[i][0], a, bd0);
                ffma2(acc2[i][1], a, bd1);
                ffma2(acc2[i][2], a, bd2);
                ffma2(acc2[i][3], a, bd3);
            }
        }
    }

    // ---- epilogue B: write g ----
#pragma unroll
    for (int i = 0; i < 4; i++) {
        float lo[4], hi[4];
#pragma unroll
        for (int j = 0; j < 4; j++) unpack2(acc2[i][j], lo[j], hi[j]);
        int g0 = mBase + ty * 8 + 2 * i, g1 = g0 + 1;
        if (g0 < n)
            *(float4*)&g_g[(size_t)g0 * 64 + tx * 4] = make_float4(lo[0], lo[1], lo[2], lo[3]);
        if (g1 < n)
            *(float4*)&g_g[(size_t)g1 * 64 + tx * 4] = make_float4(hi[0], hi[1], hi[2], hi[3]);
    }
}

// ---------------- K7: out = rsqrt(deg_in)*sum g[src] + bias2  (unroll 4) ----------------
__global__ void agg3_kernel(const float* __restrict__ bias2,
                            float* __restrict__ out, int n) {
    int gw   = (blockIdx.x * blockDim.x + threadIdx.x) >> 5;
    int lane = threadIdx.x & 31;
    if (gw >= n) return;
    int beg = g_rowoff[gw * RNUM], end = g_rowoff[gw * RNUM + RNUM];

    float a0 = 0.f, a1 = 0.f;
    int e = beg;
    for (; e + 3 < end; e += 4) {
        int p0 = g_csr[e], p1 = g_csr[e + 1], p2 = g_csr[e + 2], p3 = g_csr[e + 3];
        const float* h0 = &g_g[(size_t)p0 * 64];
        const float* h1 = &g_g[(size_t)p1 * 64];
        const float* h2 = &g_g[(size_t)p2 * 64];
        const float* h3 = &g_g[(size_t)p3 * 64];
        float v0 = h0[lane], v1 = h1[lane], v2 = h2[lane], v3 = h3[lane];
        float u0 = h0[lane + 32], u1 = h1[lane + 32], u2 = h2[lane + 32], u3 = h3[lane + 32];
        a0 += (v0 + v1) + (v2 + v3);
        a1 += (u0 + u1) + (u2 + u3);
    }
    for (; e < end; e++) {
        const float* h = &g_g[(size_t)g_csr[e] * 64];
        a0 += h[lane];
        a1 += h[lane + 32];
    }
    float sc = rsqrtf((float)max(end - beg, 1));
    out[(size_t)gw * 64 + lane]      = a0 * sc + bias2[lane];
    out[(size_t)gw * 64 + lane + 32] = a1 * sc + bias2[lane + 32];
}

// ---------------- launch ----------------
extern "C" void kernel_launch(void* const* d_in, const int* in_sizes, int n_in,
                              void* d_out, int out_size) {
    const float* x     = (const float*)d_in[0];
    const int*   ei    = (const int*)d_in[1];   // int32 (JAX x64 disabled)
    const int*   et    = (const int*)d_in[3];   // int32
    const float* basis = (const float*)d_in[4];
    const float* comp  = (const float*)d_in[5];
    const float* loopw = (const float*)d_in[6];
    const float* bias1 = (const float*)d_in[7];
    const float* w2    = (const float*)d_in[8];
    const float* bias2 = (const float*)d_in[9];
    float* out = (float*)d_out;

    int n = in_sizes[0] / 64;    // 50000
    int e = in_sizes[1] / 2;     // 1000000

    zero_kernel<<<(NPAD2 + 255) / 256, 256>>>(n);
    wcat_kernel<<<(JTOT * 64 + 255) / 256, 256>>>(basis, comp, loopw);
    deg_kernel<<<(e / 2 + 255) / 256, 256>>>(ei, et, e);
    scan1_kernel<<<NBLK2, 256>>>();
    scan2_kernel<<<1, 1024>>>();
    scan3_kernel<<<NBLK2, 256>>>();
    fill_kernel<<<(e / 2 + 255) / 256, 256>>>(ei, et, e);

    aggz_kernel<<<(n * 32 + 255) / 256, 256>>>(x, n);
    gemmf_kernel<<<(n + 127) / 128, 256>>>(bias1, w2, n);
    agg3_kernel<<<(n * 32 + 255) / 256, 256>>>(bias2, out, n);
}

// round 13
// speedup vs baseline: 1.0478x; 1.0478x over previous
#include <cuda_runtime.h>
#include <cstdint>

// Problem constants
#define NMAX 50000
#define EMAX 1000000
#define RNUM 8
#define BNUM 30
#define JTOT 576            // 8*64 relation cols + 64 self-loop cols
#define NSEG (NMAX * RNUM)  // 400000 (dst,relation) segments
#define SCHUNK 512
#define NBLK2 782           // ceil(400000/512)
#define NPAD2 (NBLK2 * SCHUNK)   // 400384

// ---------------- static device scratch ----------------
__device__ float g_Wtmp[JTOT * 64];              // Wcat [kk][o]
__device__ float g_Wcat2[JTOT * 64];             // Wcat @ W2 [kk][o]
__device__ float g_bias12[64];                   // bias1 @ W2
__device__ float g_z[(size_t)NMAX * JTOT];       // per-dst relation sums | self x
__device__ float g_g[(size_t)NMAX * 64];         // s * (z@Wcat2 + bias12)
__device__ int   g_deg_out[NMAX];
__device__ int   g_deg[NPAD2];                   // per-(dst,rel) counts, zero-padded
__device__ int   g_cursor[NSEG];
__device__ int   g_rowoff[NSEG + 1];
__device__ int   g_bsum[NBLK2];
__device__ int   g_boff[NBLK2];
__device__ int   g_csr[EMAX];                    // bare src index

// ---------------- f32x2 packed-FMA helpers ----------------
typedef unsigned long long ull;
__device__ __forceinline__ ull pack2(float lo, float hi) {
    ull r; asm("mov.b64 %0,{%1,%2};" : "=l"(r) : "f"(lo), "f"(hi)); return r;
}
__device__ __forceinline__ void unpack2(ull v, float& lo, float& hi) {
    asm("mov.b64 {%0,%1},%2;" : "=f"(lo), "=f"(hi) : "l"(v));
}
__device__ __forceinline__ void ffma2(ull& d, ull a, ull b) {
    asm("fma.rn.f32x2 %0,%1,%2,%0;" : "+l"(d) : "l"(a), "l"(b));
}

// ---------------- K0: zero counters ----------------
__global__ void zero_kernel(int n) {
    int i = blockIdx.x * blockDim.x + threadIdx.x;
    if (i < NPAD2) g_deg[i] = 0;
    if (i < NSEG) g_cursor[i] = 0;
    if (i < n) g_deg_out[i] = 0;
    if (i == 0) g_rowoff[0] = 0;
}

// ---------------- K1: Wcat (relation weights | loop weights) ----------------
__global__ void wcat_kernel(const float* __restrict__ basis,
                            const float* __restrict__ comp,
                            const float* __restrict__ loopw) {
    int idx = blockIdx.x * blockDim.x + threadIdx.x;
    if (idx >= JTOT * 64) return;
    int o = idx & 63;
    int kk = idx >> 6;
    if (kk < RNUM * 64) {
        int r = kk >> 6, i = kk & 63;
        float s = 0.f;
#pragma unroll
        for (int b = 0; b < BNUM; b++)
            s += comp[r * BNUM + b] * basis[(b * 64 + i) * 64 + o];
        g_Wtmp[kk * 64 + o] = s;
    } else {
        int i = kk - RNUM * 64;
        g_Wtmp[kk * 64 + o] = loopw[i * 64 + o];
    }
}

// ---------------- K1b: Wcat2 = Wcat @ W2, bias12 = bias1 @ W2 ----------------
__global__ void wcat2_kernel(const float* __restrict__ w2,
                             const float* __restrict__ bias1) {
    int idx = blockIdx.x * blockDim.x + threadIdx.x;
    if (idx >= JTOT * 64) return;
    int o = idx & 63;
    int kk = idx >> 6;
    float s = 0.f;
#pragma unroll 8
    for (int k = 0; k < 64; k++)
        s += g_Wtmp[kk * 64 + k] * w2[k * 64 + o];
    g_Wcat2[kk * 64 + o] = s;
    if (idx < 64) {
        float b = 0.f;
#pragma unroll 8
        for (int k = 0; k < 64; k++)
            b += bias1[k] * w2[k * 64 + idx];
        g_bias12[idx] = b;
    }
}

// ---------------- K2: counts per (dst,rel) segment + out-degree ----------------
__global__ void deg_kernel(const int* __restrict__ ei,
                           const int* __restrict__ et, int e) {
    int i = blockIdx.x * blockDim.x + threadIdx.x;
    if (i < e) {
        atomicAdd(&g_deg_out[ei[i]], 1);
        atomicAdd(&g_deg[ei[e + i] * RNUM + et[i]], 1);
    }
}

// ---------------- K3a: per-block sums (782 blocks x 512 elems) ----------------
__global__ void scan1_kernel() {
    __shared__ int ws[8];
    int b = blockIdx.x, tid = threadIdx.x, lane = tid & 31, wid = tid >> 5;
    int2 v = *(const int2*)&g_deg[b * SCHUNK + tid * 2];
    int s = v.x + v.y;
#pragma unroll
    for (int off = 16; off >= 1; off >>= 1)
        s += __shfl_down_sync(0xFFFFFFFFu, s, off);
    if (lane == 0) ws[wid] = s;
    __syncthreads();
    if (tid == 0) {
        int t = 0;
#pragma unroll
        for (int j = 0; j < 8; j++) t += ws[j];
        g_bsum[b] = t;
    }
}

// ---------------- K3b: exclusive scan of block sums ----------------
__global__ void scan2_kernel() {
    __shared__ int wsum[32];
    int tid = threadIdx.x, lane = tid & 31, wid = tid >> 5;
    int v = (tid < NBLK2) ? g_bsum[tid] : 0;
    int sc = v;
#pragma unroll
    for (int off = 1; off < 32; off <<= 1) {
        int t = __shfl_up_sync(0xFFFFFFFFu, sc, off);
        if (lane >= off) sc += t;
    }
    if (lane == 31) wsum[wid] = sc;
    __syncthreads();
    if (wid == 0) {
        int w = wsum[lane];
        int s2 = w;
#pragma unroll
        for (int off = 1; off < 32; off <<= 1) {
            int t = __shfl_up_sync(0xFFFFFFFFu, s2, off);
            if (lane >= off) s2 += t;
        }
        wsum[lane] = s2 - w;
    }
    __syncthreads();
    if (tid < NBLK2) g_boff[tid] = sc - v + wsum[wid];
}

// ---------------- K3c: per-block scan + global offset -> rowoff ----------------
__global__ void scan3_kernel() {
    __shared__ int ws[8];
    __shared__ int wx[8];
    int b = blockIdx.x, tid = threadIdx.x, lane = tid & 31, wid = tid >> 5;
    int i0 = b * SCHUNK + tid * 2;
    int2 v = *(const int2*)&g_deg[i0];
    int ps = v.x + v.y;
    int sc = ps;
#pragma unroll
    for (int off = 1; off < 32; off <<= 1) {
        int t = __shfl_up_sync(0xFFFFFFFFu, sc, off);
        if (lane >= off) sc += t;
    }
    if (lane == 31) ws[wid] = sc;
    __syncthreads();
    if (tid == 0) {
        int run = 0;
#pragma unroll
        for (int j = 0; j < 8; j++) { wx[j] = run; run += ws[j]; }
    }
    __syncthreads();
    int excl = (sc - ps) + wx[wid] + g_boff[b];
    int r1 = excl + v.x;
    int r2 = r1 + v.y;
    if (i0 < NSEG)     g_rowoff[i0 + 1] = r1;
    if (i0 + 1 < NSEG) g_rowoff[i0 + 2] = r2;
}

// ---------------- K4: fill CSR (sorted by (dst, rel)) ----------------
__global__ void fill_kernel(const int* __restrict__ ei,
                            const int* __restrict__ et, int e) {
    int i = blockIdx.x * blockDim.x + threadIdx.x;
    if (i < e) {
        int seg = ei[e + i] * RNUM + et[i];
        int pos = g_rowoff[seg] + atomicAdd(&g_cursor[seg], 1);
        g_csr[pos] = ei[i];
    }
}

// ---------------- K5: aggregate x[src] per (dst,rel) segment -> z ----------------
__global__ void aggz_kernel(const float* __restrict__ x, int n) {
    int gw   = (blockIdx.x * blockDim.x + threadIdx.x) >> 5;
    int lane = threadIdx.x & 31;
    if (gw >= n) return;
    float* zr = &g_z[(size_t)gw * JTOT];
    int base = gw * RNUM;
    int beg = g_rowoff[base];
#pragma unroll 1
    for (int r = 0; r < RNUM; r++) {
        int end = g_rowoff[base + r + 1];
        float a0 = 0.f, a1 = 0.f;
        int e = beg;
        for (; e + 1 < end; e += 2) {
            int p0 = g_csr[e], p1 = g_csr[e + 1];
            const float* s0 = &x[(size_t)p0 * 64];
            const float* s1 = &x[(size_t)p1 * 64];
            float v00 = s0[lane],      v10 = s1[lane];
            float v01 = s0[lane + 32], v11 = s1[lane + 32];
            a0 += v00 + v10;
            a1 += v01 + v11;
        }
        if (e < end) {
            const float* s0 = &x[(size_t)g_csr[e] * 64];
            a0 += s0[lane];
            a1 += s0[lane + 32];
        }
        zr[r * 64 + lane]      = a0;
        zr[r * 64 + lane + 32] = a1;
        beg = end;
    }
    zr[512 + lane]      = x[(size_t)gw * 64 + lane];
    zr[512 + lane + 32] = x[(size_t)gw * 64 + lane + 32];
}

// ---------------- K6: GEMM: g = rsqrt(deg_out) * (z @ Wcat2 + bias12) ----------------
__global__ __launch_bounds__(256) void gemm_kernel(int M) {
    __shared__ float shA[32][132];   // [k][m], padded
    __shared__ float shB[32][64];

    int tid = threadIdx.x;
    int tx = tid & 15, ty = tid >> 4;
    int mBase = blockIdx.x * 128;
    int rowL = tid >> 1, half = tid & 1;
    int gr = mBase + rowL;

    ull acc[4][4] = {};
    for (int k0 = 0; k0 < JTOT; k0 += 32) {
        __syncthreads();
#pragma unroll
        for (int q = 0; q < 4; q++) {
            int kk = half * 16 + q * 4;
            float4 v = make_float4(0.f, 0.f, 0.f, 0.f);
            if (gr < M) v = *(const float4*)&g_z[(size_t)gr * JTOT + k0 + kk];
            shA[kk][rowL] = v.x; shA[kk + 1][rowL] = v.y;
            shA[kk + 2][rowL] = v.z; shA[kk + 3][rowL] = v.w;
        }
        {
            int f = tid * 8, kr = f >> 6, c = f & 63;
            *(float4*)&shB[kr][c]     = *(const float4*)&g_Wcat2[(size_t)(k0 + kr) * 64 + c];
            *(float4*)&shB[kr][c + 4] = *(const float4*)&g_Wcat2[(size_t)(k0 + kr) * 64 + c + 4];
        }
        __syncthreads();
#pragma unroll
        for (int k = 0; k < 32; k++) {
            float4 b = *(const float4*)&shB[k][tx * 4];
            ull bd0 = pack2(b.x, b.x), bd1 = pack2(b.y, b.y);
            ull bd2 = pack2(b.z, b.z), bd3 = pack2(b.w, b.w);
#pragma unroll
            for (int i = 0; i < 4; i++) {
                ull a = *(const ull*)&shA[k][ty * 8 + 2 * i];
                ffma2(acc[i][0], a, bd0);
                ffma2(acc[i][1], a, bd1);
                ffma2(acc[i][2], a, bd2);
                ffma2(acc[i][3], a, bd3);
            }
        }
    }
    float4 bv = *(const float4*)&g_bias12[tx * 4];
#pragma unroll
    for (int i = 0; i < 4; i++) {
        float lo[4], hi[4];
#pragma unroll
        for (int j = 0; j < 4; j++) unpack2(acc[i][j], lo[j], hi[j]);
        int g0 = mBase + ty * 8 + 2 * i, g1 = g0 + 1;
        if (g0 < M) {
            float s = rsqrtf((float)max(g_deg_out[g0], 1));
            *(float4*)&g_g[(size_t)g0 * 64 + tx * 4] =
                make_float4((lo[0] + bv.x) * s, (lo[1] + bv.y) * s,
                            (lo[2] + bv.z) * s, (lo[3] + bv.w) * s);
        }
        if (g1 < M) {
            float s = rsqrtf((float)max(g_deg_out[g1], 1));
            *(float4*)&g_g[(size_t)g1 * 64 + tx * 4] =
                make_float4((hi[0] + bv.x) * s, (hi[1] + bv.y) * s,
                            (hi[2] + bv.z) * s, (hi[3] + bv.w) * s);
        }
    }
}

// ---------------- K7: out = rsqrt(deg_in)*sum g[src] + bias2  (unroll 4) ----------------
__global__ void agg3_kernel(const float* __restrict__ bias2,
                            float* __restrict__ out, int n) {
    int gw   = (blockIdx.x * blockDim.x + threadIdx.x) >> 5;
    int lane = threadIdx.x & 31;
    if (gw >= n) return;
    int beg = g_rowoff[gw * RNUM], end = g_rowoff[gw * RNUM + RNUM];

    float a0 = 0.f, a1 = 0.f;
    int e = beg;
    for (; e + 3 < end; e += 4) {
        int p0 = g_csr[e], p1 = g_csr[e + 1], p2 = g_csr[e + 2], p3 = g_csr[e + 3];
        const float* h0 = &g_g[(size_t)p0 * 64];
        const float* h1 = &g_g[(size_t)p1 * 64];
        const float* h2 = &g_g[(size_t)p2 * 64];
        const float* h3 = &g_g[(size_t)p3 * 64];
        float v0 = h0[lane], v1 = h1[lane], v2 = h2[lane], v3 = h3[lane];
        float u0 = h0[lane + 32], u1 = h1[lane + 32], u2 = h2[lane + 32], u3 = h3[lane + 32];
        a0 += (v0 + v1) + (v2 + v3);
        a1 += (u0 + u1) + (u2 + u3);
    }
    for (; e < end; e++) {
        const float* h = &g_g[(size_t)g_csr[e] * 64];
        a0 += h[lane];
        a1 += h[lane + 32];
    }
    float sc = rsqrtf((float)max(end - beg, 1));
    out[(size_t)gw * 64 + lane]      = a0 * sc + bias2[lane];
    out[(size_t)gw * 64 + lane + 32] = a1 * sc + bias2[lane + 32];
}

// ---------------- launch ----------------
extern "C" void kernel_launch(void* const* d_in, const int* in_sizes, int n_in,
                              void* d_out, int out_size) {
    const float* x     = (const float*)d_in[0];
    const int*   ei    = (const int*)d_in[1];   // int32 (JAX x64 disabled)
    const int*   et    = (const int*)d_in[3];   // int32
    const float* basis = (const float*)d_in[4];
    const float* comp  = (const float*)d_in[5];
    const float* loopw = (const float*)d_in[6];
    const float* bias1 = (const float*)d_in[7];
    const float* w2    = (const float*)d_in[8];
    const float* bias2 = (const float*)d_in[9];
    float* out = (float*)d_out;

    int n = in_sizes[0] / 64;    // 50000
    int e = in_sizes[1] / 2;     // 1000000

    zero_kernel<<<(NPAD2 + 255) / 256, 256>>>(n);
    wcat_kernel<<<(JTOT * 64 + 255) / 256, 256>>>(basis, comp, loopw);
    wcat2_kernel<<<(JTOT * 64 + 255) / 256, 256>>>(w2, bias1);
    deg_kernel<<<(e + 255) / 256, 256>>>(ei, et, e);
    scan1_kernel<<<NBLK2, 256>>>();
    scan2_kernel<<<1, 1024>>>();
    scan3_kernel<<<NBLK2, 256>>>();
    fill_kernel<<<(e + 255) / 256, 256>>>(ei, et, e);

    aggz_kernel<<<(n * 32 + 255) / 256, 256>>>(x, n);
    gemm_kernel<<<(n + 127) / 128, 256>>>(n);
    agg3_kernel<<<(n * 32 + 255) / 256, 256>>>(bias2, out, n);
}